// round 11
// baseline (speedup 1.0000x reference)
#include <cuda_runtime.h>
#include <cuda_fp16.h>
#include <cstdint>

#define NN 40000
#define EE 640000
#define RRL 8
#define HH 128
#define CC 64
#define NTILES 313          // ceil(40000/128)
#define MAXDEG 64
#define PAD2 68
#define IDXMASK 0x7FFFF

// ---------------- scratch (__device__ globals; no allocation) ----------------
__device__ int   g_cursor[NN];
__device__ int   g_edgepad[NN * MAXDEG];              // (rel<<20)|(rel*NN+src), 10 MB
__device__ uint32_t g_h[(size_t)NTILES * 128 * 64];   // layer-1 out, half2-packed [row][64]
__device__ __half g_w2t[9 * CC * HH];                 // W2^T / root2^T fp16 [m][c][k]
__device__ __half g_hall[(size_t)RRL * NN * CC];      // h @ W2[r] fp16, permuted slots

// ---------------- single-pass edge bucketing (+ one-shot W2/root2 fp16 fold) ----------------
__global__ void k_perm(const int* __restrict__ ei, const int* __restrict__ et,
                       const float* __restrict__ W2, const float* __restrict__ root2) {
    int gid = blockIdx.x * blockDim.x + threadIdx.x;
    if (gid < 9 * CC * HH) {
        int m = gid >> 13;
        int rem = gid & 8191;
        int c = rem >> 7;
        int k = rem & 127;
        float v = (m < 8) ? W2[((size_t)m * HH + k) * CC + c] : root2[(size_t)k * CC + c];
        g_w2t[gid] = __float2half_rn(v);
    }
    if (gid >= EE) return;
    int dst = ei[EE + gid];
    int rel = et[gid];
    int src = ei[gid];
    int pos = atomicAdd(&g_cursor[dst], 1);
    if (pos < MAXDEG) g_edgepad[dst * MAXDEG + pos] = (rel << 20) | (rel * NN + src);
}

// ---------------- layer 1: warp per dst, 8-deep MLP, writes fp16 (half2-packed) ----------------
__global__ void k_layer1(const float* __restrict__ W1, const float* __restrict__ root1,
                         const float* __restrict__ b1) {
    int w = (blockIdx.x * blockDim.x + threadIdx.x) >> 5;
    int lane = threadIdx.x & 31;
    if (w >= NN) return;
    int cnt = g_cursor[w];
    cnt = cnt < MAXDEG ? cnt : MAXDEG;
    const int* pad = g_edgepad + w * MAXDEG;

    // per-(dst,rel) inverse counts via ballots; lane r holds 1/max(cnt_r,1)
    int e0 = (lane < cnt) ? pad[lane] : -1;
    int e1 = (lane + 32 < cnt) ? pad[lane + 32] : -1;
    int r0 = e0 >> 20, r1 = e1 >> 20;
    float myinv = 1.0f;
#pragma unroll
    for (int r = 0; r < 8; r++) {
        unsigned b0 = __ballot_sync(0xFFFFFFFFu, r0 == r);
        unsigned b1 = __ballot_sync(0xFFFFFFFFu, r1 == r);
        if (lane == r) {
            int c = __popc(b0) + __popc(b1);
            myinv = 1.0f / (float)(c > 0 ? c : 1);
        }
    }

    float4 acc = ((const float4*)root1)[w * 32 + lane];
    float4 bb = ((const float4*)b1)[lane];
    acc.x += bb.x; acc.y += bb.y; acc.z += bb.z; acc.w += bb.w;
    const float4* W1v = (const float4*)W1;
    int i = 0;
    for (; i + 8 <= cnt; i += 8) {
        int e[8]; float4 v[8];
#pragma unroll
        for (int j = 0; j < 8; j++) e[j] = pad[i + j];
#pragma unroll
        for (int j = 0; j < 8; j++)
            v[j] = W1v[(size_t)(e[j] & IDXMASK) * 32 + lane];
#pragma unroll
        for (int j = 0; j < 8; j++) {
            float s = __shfl_sync(0xFFFFFFFFu, myinv, e[j] >> 20);
            acc.x += v[j].x * s;
            acc.y += v[j].y * s;
            acc.z += v[j].z * s;
            acc.w += v[j].w * s;
        }
    }
    for (; i < cnt; i++) {
        int e = pad[i];
        float s = __shfl_sync(0xFFFFFFFFu, myinv, e >> 20);
        float4 v = W1v[(size_t)(e & IDXMASK) * 32 + lane];
        acc.x += v.x * s; acc.y += v.y * s; acc.z += v.z * s; acc.w += v.w * s;
    }
    __half2 p0 = __floats2half2_rn(fmaxf(acc.x, 0.0f), fmaxf(acc.y, 0.0f));
    __half2 p1 = __floats2half2_rn(fmaxf(acc.z, 0.0f), fmaxf(acc.w, 0.0f));
    ((uint2*)g_h)[w * 32 + lane] = make_uint2(*(uint32_t*)&p0, *(uint32_t*)&p1);
}

// ---------------- GEMM via fp16 mma.sync m16n8k16: A staged once, 3 r-slices per CTA ----------------
// g_hall rows: half2-slot s holds logical c-pair (s&7)*8 + (s>>3)*2 (layer2 inverts).
#define SM_TOTAL ((128 + 64) * PAD2 * 4)   // 52224 bytes

__global__ void __launch_bounds__(256) k_gemm(const float* __restrict__ b2,
                                              float* __restrict__ out) {
    extern __shared__ uint32_t sm32[];
    uint32_t* As = sm32;                // [128][PAD2] half2 words
    uint32_t* Bs = sm32 + 128 * PAD2;   // [64][PAD2]  half2 words (B^T: [c][k])
    int t = threadIdx.x;
    int tile = blockIdx.x;
    int rbase = blockIdx.y * 3;

    const uint4* asrc = (const uint4*)(g_h + (size_t)tile * 128 * 64);
#pragma unroll
    for (int j = 0; j < 8; j++) {
        int f = t + j * 256;           // 0..2047
        int row = f >> 4, q = f & 15;
        *(uint4*)&As[row * PAD2 + (q << 2)] = asrc[f];
    }

    int warp = t >> 5, lane = t & 31;
    int g = lane >> 2;        // groupID 0..7
    int tig = lane & 3;       // threadID_in_group
    int rA = warp * 16 + g;
    int n0 = tile * 128 + warp * 16 + g;
    int n1 = n0 + 8;

    for (int rr = 0; rr < 3; rr++) {
        int r = rbase + rr;
        __syncthreads();      // Bs overwrite safety + first-iter As visibility
        const uint4* bsrc = (const uint4*)(g_w2t + (size_t)r * CC * HH);
#pragma unroll
        for (int j = 0; j < 4; j++) {
            int f = t + j * 256;       // 0..1023
            int row = f >> 4, q = f & 15;
            *(uint4*)&Bs[row * PAD2 + (q << 2)] = bsrc[f];
        }
        __syncthreads();

        float acc[8][4];
#pragma unroll
        for (int nt = 0; nt < 8; nt++)
#pragma unroll
            for (int q = 0; q < 4; q++) acc[nt][q] = 0.0f;

#pragma unroll
        for (int ks = 0; ks < 8; ks++) {
            int j0 = ks * 8 + tig;     // half2-word index; k = 2*j0
            uint32_t a0 = As[rA * PAD2 + j0];
            uint32_t a1 = As[(rA + 8) * PAD2 + j0];
            uint32_t a2 = As[rA * PAD2 + j0 + 4];
            uint32_t a3 = As[(rA + 8) * PAD2 + j0 + 4];
#pragma unroll
            for (int nt = 0; nt < 8; nt++) {
                int brow = nt * 8 + g;
                uint32_t b0 = Bs[brow * PAD2 + j0];
                uint32_t b1_ = Bs[brow * PAD2 + j0 + 4];
                asm volatile(
                    "mma.sync.aligned.m16n8k16.row.col.f32.f16.f16.f32 "
                    "{%0,%1,%2,%3}, {%4,%5,%6,%7}, {%8,%9}, {%0,%1,%2,%3};"
                    : "+f"(acc[nt][0]), "+f"(acc[nt][1]), "+f"(acc[nt][2]), "+f"(acc[nt][3])
                    : "r"(a0), "r"(a1), "r"(a2), "r"(a3), "r"(b0), "r"(b1_));
            }
        }

        if (r < 8) {
            __half2* hall2 = (__half2*)g_hall;
            uint32_t p0[8], p1[8];
#pragma unroll
            for (int nt = 0; nt < 8; nt++) {
                __half2 h0 = __floats2half2_rn(acc[nt][0], acc[nt][1]);
                __half2 h1 = __floats2half2_rn(acc[nt][2], acc[nt][3]);
                p0[nt] = *(uint32_t*)&h0;
                p1[nt] = *(uint32_t*)&h1;
            }
            if (n0 < NN) {
                __half2* rb = hall2 + ((size_t)r * NN + n0) * 32 + tig * 8;
                *(uint4*)rb       = make_uint4(p0[0], p0[1], p0[2], p0[3]);
                *(uint4*)(rb + 4) = make_uint4(p0[4], p0[5], p0[6], p0[7]);
            }
            if (n1 < NN) {
                __half2* rb = hall2 + ((size_t)r * NN + n1) * 32 + tig * 8;
                *(uint4*)rb       = make_uint4(p1[0], p1[1], p1[2], p1[3]);
                *(uint4*)(rb + 4) = make_uint4(p1[4], p1[5], p1[6], p1[7]);
            }
        } else {
#pragma unroll
            for (int nt = 0; nt < 8; nt++) {
                int c = nt * 8 + tig * 2;
                float2 bb = *(const float2*)&b2[c];
                if (n0 < NN) *(float2*)&out[(size_t)n0 * CC + c] = make_float2(acc[nt][0] + bb.x, acc[nt][1] + bb.y);
                if (n1 < NN) *(float2*)&out[(size_t)n1 * CC + c] = make_float2(acc[nt][2] + bb.x, acc[nt][3] + bb.y);
            }
        }
    }
}

// ---------------- layer 2: 2 dst per warp (16 lanes each), register-resident edges ----------------
__global__ void k_layer2(float* __restrict__ out) {
    int gw = (blockIdx.x * blockDim.x + threadIdx.x) >> 5;   // warp id, 20000 total
    int lane = threadIdx.x & 31;
    int half = lane >> 4;
    int hl = lane & 15;
    int w = gw * 2 + half;          // dst node (always < NN: 2*20000 = NN exactly)

    int cnt = g_cursor[w];
    cnt = cnt < MAXDEG ? cnt : MAXDEG;
    const int* pad = g_edgepad + w * MAXDEG;

    // preload up to 64 edges into 4 regs/lane
    int e0 = (hl      < cnt) ? pad[hl]      : -1;
    int e1 = (hl + 16 < cnt) ? pad[hl + 16] : -1;
    int e2 = (hl + 32 < cnt) ? pad[hl + 32] : -1;
    int e3 = (hl + 48 < cnt) ? pad[hl + 48] : -1;
    int r0 = e0 >> 20, r1 = e1 >> 20, r2 = e2 >> 20, r3 = e3 >> 20;

    // per-(dst,rel) inverse counts (converged full-warp ballots, per-half popc)
    unsigned hm = half ? 0xFFFF0000u : 0x0000FFFFu;
    float myinv = 1.0f;
#pragma unroll
    for (int r = 0; r < 8; r++) {
        unsigned b0 = __ballot_sync(0xFFFFFFFFu, r0 == r);
        unsigned b1 = __ballot_sync(0xFFFFFFFFu, r1 == r);
        unsigned b2 = __ballot_sync(0xFFFFFFFFu, r2 == r);
        unsigned b3 = __ballot_sync(0xFFFFFFFFu, r3 == r);
        if (hl == r) {
            int c = __popc(b0 & hm) + __popc(b1 & hm) + __popc(b2 & hm) + __popc(b3 & hm);
            myinv = 1.0f / (float)(c > 0 ? c : 1);
        }
    }
    // per-lane scales for its 4 edges (segment shuffles; full warp still converged)
    float s0 = __shfl_sync(0xFFFFFFFFu, myinv, r0 & 7, 16);
    float s1 = __shfl_sync(0xFFFFFFFFu, myinv, r1 & 7, 16);
    float s2 = __shfl_sync(0xFFFFFFFFu, myinv, r2 & 7, 16);
    float s3 = __shfl_sync(0xFFFFFFFFu, myinv, r3 & 7, 16);

    // two half2 slots per lane: 2hl, 2hl+1
    int sl0 = 2 * hl, sl1 = 2 * hl + 1;
    int cl0 = ((sl0 & 7) << 3) + ((sl0 >> 3) << 1);
    int cl1 = ((sl1 & 7) << 3) + ((sl1 >> 3) << 1);
    float2 acc0 = *(const float2*)&out[(size_t)w * CC + cl0];
    float2 acc1 = *(const float2*)&out[(size_t)w * CC + cl1];
    const __half2* hv = (const __half2*)g_hall;

    // divergent per-half loops: only segment shuffles inside (mask = own half)
#pragma unroll
    for (int seg = 0; seg < 4; seg++) {
        int base = seg * 16;
        if (base >= cnt) break;
        int m = cnt - base; m = m < 16 ? m : 16;
        int ee = (seg == 0) ? e0 : (seg == 1) ? e1 : (seg == 2) ? e2 : e3;
        float ss = (seg == 0) ? s0 : (seg == 1) ? s1 : (seg == 2) ? s2 : s3;
#pragma unroll 4
        for (int j = 0; j < m; j++) {
            int e = __shfl_sync(hm, ee, j, 16);
            float s = __shfl_sync(hm, ss, j, 16);
            uint2 raw = *(const uint2*)(hv + (size_t)(e & IDXMASK) * 32 + sl0);
            float2 f0 = __half22float2(*(__half2*)&raw.x);
            float2 f1 = __half22float2(*(__half2*)&raw.y);
            acc0.x += f0.x * s; acc0.y += f0.y * s;
            acc1.x += f1.x * s; acc1.y += f1.y * s;
        }
    }
    *(float2*)&out[(size_t)w * CC + cl0] = acc0;
    *(float2*)&out[(size_t)w * CC + cl1] = acc1;
}

// ---------------- launch ----------------
extern "C" void kernel_launch(void* const* d_in, const int* in_sizes, int n_in,
                              void* d_out, int out_size) {
    (void)in_sizes; (void)n_in; (void)out_size;
    const int*   ei    = (const int*)d_in[0];
    const int*   et    = (const int*)d_in[1];
    const float* W1    = (const float*)d_in[2];
    const float* root1 = (const float*)d_in[3];
    const float* b1    = (const float*)d_in[4];
    const float* W2    = (const float*)d_in[5];
    const float* root2 = (const float*)d_in[6];
    const float* b2    = (const float*)d_in[7];
    float* out = (float*)d_out;

    void* p_cursor = nullptr;
    cudaGetSymbolAddress(&p_cursor, g_cursor);
    cudaMemsetAsync(p_cursor, 0, NN * sizeof(int));

    k_perm<<<(EE + 255) / 256, 256>>>(ei, et, W2, root2);
    k_layer1<<<NN / 8, 256>>>(W1, root1, b1);
    cudaFuncSetAttribute(k_gemm, cudaFuncAttributeMaxDynamicSharedMemorySize, SM_TOTAL);
    k_gemm<<<dim3(NTILES, 3), 256, SM_TOTAL>>>(b2, out);
    k_layer2<<<2500, 256>>>(out);
}

// round 12
// speedup vs baseline: 1.0785x; 1.0785x over previous
#include <cuda_runtime.h>
#include <cuda_fp16.h>
#include <cstdint>

#define NN 40000
#define EE 640000
#define RRL 8
#define HH 128
#define CC 64
#define NTILES 313          // ceil(40000/128)
#define MAXDEG 64
#define PAD2 68
#define IDXMASK 0x7FFFF

// ---------------- scratch (__device__ globals; no allocation) ----------------
__device__ int   g_cursor[NN];
__device__ int   g_edgepad[NN * MAXDEG];              // (rel<<20)|(rel*NN+src), 10 MB
__device__ uint32_t g_h[(size_t)NTILES * 128 * 64];   // layer-1 out, half2-packed [row][64]
__device__ __half g_w2t[9 * CC * HH];                 // W2^T / root2^T fp16 [m][c][k]
__device__ __half g_hall[(size_t)RRL * NN * CC];      // h @ W2[r] fp16, permuted slots

// ---------------- single-pass edge bucketing (+ one-shot W2/root2 fp16 fold) ----------------
__global__ void k_perm(const int* __restrict__ ei, const int* __restrict__ et,
                       const float* __restrict__ W2, const float* __restrict__ root2) {
    int gid = blockIdx.x * blockDim.x + threadIdx.x;
    if (gid < 9 * CC * HH) {
        int m = gid >> 13;
        int rem = gid & 8191;
        int c = rem >> 7;
        int k = rem & 127;
        float v = (m < 8) ? W2[((size_t)m * HH + k) * CC + c] : root2[(size_t)k * CC + c];
        g_w2t[gid] = __float2half_rn(v);
    }
    if (gid >= EE) return;
    int dst = ei[EE + gid];
    int rel = et[gid];
    int src = ei[gid];
    int pos = atomicAdd(&g_cursor[dst], 1);
    if (pos < MAXDEG) g_edgepad[dst * MAXDEG + pos] = (rel << 20) | (rel * NN + src);
}

// ---------------- layer 1: warp per dst, 8-deep MLP, writes fp16 (half2-packed) ----------------
__global__ void k_layer1(const float* __restrict__ W1, const float* __restrict__ root1,
                         const float* __restrict__ b1) {
    int w = (blockIdx.x * blockDim.x + threadIdx.x) >> 5;
    int lane = threadIdx.x & 31;
    if (w >= NN) return;
    int cnt = g_cursor[w];
    cnt = cnt < MAXDEG ? cnt : MAXDEG;
    const int* pad = g_edgepad + w * MAXDEG;

    // per-(dst,rel) inverse counts via ballots; lane r holds 1/max(cnt_r,1)
    int e0 = (lane < cnt) ? pad[lane] : -1;
    int e1 = (lane + 32 < cnt) ? pad[lane + 32] : -1;
    int r0 = e0 >> 20, r1 = e1 >> 20;
    float myinv = 1.0f;
#pragma unroll
    for (int r = 0; r < 8; r++) {
        unsigned b0 = __ballot_sync(0xFFFFFFFFu, r0 == r);
        unsigned b1 = __ballot_sync(0xFFFFFFFFu, r1 == r);
        if (lane == r) {
            int c = __popc(b0) + __popc(b1);
            myinv = 1.0f / (float)(c > 0 ? c : 1);
        }
    }

    float4 acc = ((const float4*)root1)[w * 32 + lane];
    float4 bb = ((const float4*)b1)[lane];
    acc.x += bb.x; acc.y += bb.y; acc.z += bb.z; acc.w += bb.w;
    const float4* W1v = (const float4*)W1;
    int i = 0;
    for (; i + 8 <= cnt; i += 8) {
        int e[8]; float4 v[8];
#pragma unroll
        for (int j = 0; j < 8; j++) e[j] = pad[i + j];
#pragma unroll
        for (int j = 0; j < 8; j++)
            v[j] = W1v[(size_t)(e[j] & IDXMASK) * 32 + lane];
#pragma unroll
        for (int j = 0; j < 8; j++) {
            float s = __shfl_sync(0xFFFFFFFFu, myinv, e[j] >> 20);
            acc.x += v[j].x * s;
            acc.y += v[j].y * s;
            acc.z += v[j].z * s;
            acc.w += v[j].w * s;
        }
    }
    for (; i < cnt; i++) {
        int e = pad[i];
        float s = __shfl_sync(0xFFFFFFFFu, myinv, e >> 20);
        float4 v = W1v[(size_t)(e & IDXMASK) * 32 + lane];
        acc.x += v.x * s; acc.y += v.y * s; acc.z += v.z * s; acc.w += v.w * s;
    }
    __half2 p0 = __floats2half2_rn(fmaxf(acc.x, 0.0f), fmaxf(acc.y, 0.0f));
    __half2 p1 = __floats2half2_rn(fmaxf(acc.z, 0.0f), fmaxf(acc.w, 0.0f));
    ((uint2*)g_h)[w * 32 + lane] = make_uint2(*(uint32_t*)&p0, *(uint32_t*)&p1);
}

// ---------------- GEMM via fp16 mma.sync m16n8k16: A staged once, 3 r-slices per CTA ----------------
// g_hall rows: half2-slot s holds logical c-pair (s&7)*8 + (s>>3)*2 (layer2 inverts).
#define SM_TOTAL ((128 + 64) * PAD2 * 4)   // 52224 bytes

__global__ void __launch_bounds__(256) k_gemm(const float* __restrict__ b2,
                                              float* __restrict__ out) {
    extern __shared__ uint32_t sm32[];
    uint32_t* As = sm32;                // [128][PAD2] half2 words
    uint32_t* Bs = sm32 + 128 * PAD2;   // [64][PAD2]  half2 words (B^T: [c][k])
    int t = threadIdx.x;
    int tile = blockIdx.x;
    int rbase = blockIdx.y * 3;

    const uint4* asrc = (const uint4*)(g_h + (size_t)tile * 128 * 64);
#pragma unroll
    for (int j = 0; j < 8; j++) {
        int f = t + j * 256;           // 0..2047
        int row = f >> 4, q = f & 15;
        *(uint4*)&As[row * PAD2 + (q << 2)] = asrc[f];
    }

    int warp = t >> 5, lane = t & 31;
    int g = lane >> 2;        // groupID 0..7
    int tig = lane & 3;       // threadID_in_group
    int rA = warp * 16 + g;
    int n0 = tile * 128 + warp * 16 + g;
    int n1 = n0 + 8;

    for (int rr = 0; rr < 3; rr++) {
        int r = rbase + rr;
        __syncthreads();      // Bs overwrite safety + first-iter As visibility
        const uint4* bsrc = (const uint4*)(g_w2t + (size_t)r * CC * HH);
#pragma unroll
        for (int j = 0; j < 4; j++) {
            int f = t + j * 256;       // 0..1023
            int row = f >> 4, q = f & 15;
            *(uint4*)&Bs[row * PAD2 + (q << 2)] = bsrc[f];
        }
        __syncthreads();

        float acc[8][4];
#pragma unroll
        for (int nt = 0; nt < 8; nt++)
#pragma unroll
            for (int q = 0; q < 4; q++) acc[nt][q] = 0.0f;

#pragma unroll
        for (int ks = 0; ks < 8; ks++) {
            int j0 = ks * 8 + tig;     // half2-word index; k = 2*j0
            uint32_t a0 = As[rA * PAD2 + j0];
            uint32_t a1 = As[(rA + 8) * PAD2 + j0];
            uint32_t a2 = As[rA * PAD2 + j0 + 4];
            uint32_t a3 = As[(rA + 8) * PAD2 + j0 + 4];
#pragma unroll
            for (int nt = 0; nt < 8; nt++) {
                int brow = nt * 8 + g;
                uint32_t b0 = Bs[brow * PAD2 + j0];
                uint32_t b1_ = Bs[brow * PAD2 + j0 + 4];
                asm volatile(
                    "mma.sync.aligned.m16n8k16.row.col.f32.f16.f16.f32 "
                    "{%0,%1,%2,%3}, {%4,%5,%6,%7}, {%8,%9}, {%0,%1,%2,%3};"
                    : "+f"(acc[nt][0]), "+f"(acc[nt][1]), "+f"(acc[nt][2]), "+f"(acc[nt][3])
                    : "r"(a0), "r"(a1), "r"(a2), "r"(a3), "r"(b0), "r"(b1_));
            }
        }

        if (r < 8) {
            __half2* hall2 = (__half2*)g_hall;
            uint32_t p0[8], p1[8];
#pragma unroll
            for (int nt = 0; nt < 8; nt++) {
                __half2 h0 = __floats2half2_rn(acc[nt][0], acc[nt][1]);
                __half2 h1 = __floats2half2_rn(acc[nt][2], acc[nt][3]);
                p0[nt] = *(uint32_t*)&h0;
                p1[nt] = *(uint32_t*)&h1;
            }
            if (n0 < NN) {
                __half2* rb = hall2 + ((size_t)r * NN + n0) * 32 + tig * 8;
                *(uint4*)rb       = make_uint4(p0[0], p0[1], p0[2], p0[3]);
                *(uint4*)(rb + 4) = make_uint4(p0[4], p0[5], p0[6], p0[7]);
            }
            if (n1 < NN) {
                __half2* rb = hall2 + ((size_t)r * NN + n1) * 32 + tig * 8;
                *(uint4*)rb       = make_uint4(p1[0], p1[1], p1[2], p1[3]);
                *(uint4*)(rb + 4) = make_uint4(p1[4], p1[5], p1[6], p1[7]);
            }
        } else {
#pragma unroll
            for (int nt = 0; nt < 8; nt++) {
                int c = nt * 8 + tig * 2;
                float2 bb = *(const float2*)&b2[c];
                if (n0 < NN) *(float2*)&out[(size_t)n0 * CC + c] = make_float2(acc[nt][0] + bb.x, acc[nt][1] + bb.y);
                if (n1 < NN) *(float2*)&out[(size_t)n1 * CC + c] = make_float2(acc[nt][2] + bb.x, acc[nt][3] + bb.y);
            }
        }
    }
}

// ---------------- layer 2: 2 dst per warp, batched 8-deep loads ----------------
__global__ void k_layer2(float* __restrict__ out) {
    int gw = (blockIdx.x * blockDim.x + threadIdx.x) >> 5;   // warp id, 20000 total
    int lane = threadIdx.x & 31;
    int half = lane >> 4;
    int hl = lane & 15;
    int w = gw * 2 + half;          // dst node (2*20000 = NN exactly)

    int cnt = g_cursor[w];
    cnt = cnt < MAXDEG ? cnt : MAXDEG;
    const int* pad = g_edgepad + w * MAXDEG;

    // preload up to 64 edges into 4 regs/lane; invalid -> rel=-1 for ballots
    bool v0 = hl < cnt, v1 = hl + 16 < cnt, v2 = hl + 32 < cnt, v3 = hl + 48 < cnt;
    int e0r = v0 ? pad[hl]      : -1;
    int e1r = v1 ? pad[hl + 16] : -1;
    int e2r = v2 ? pad[hl + 32] : -1;
    int e3r = v3 ? pad[hl + 48] : -1;
    int r0 = e0r >> 20, r1 = e1r >> 20, r2 = e2r >> 20, r3 = e3r >> 20;

    // per-(dst,rel) inverse counts (converged full-warp ballots, per-half popc)
    unsigned hm = half ? 0xFFFF0000u : 0x0000FFFFu;
    float myinv = 1.0f;
#pragma unroll
    for (int r = 0; r < 8; r++) {
        unsigned b0 = __ballot_sync(0xFFFFFFFFu, r0 == r);
        unsigned b1 = __ballot_sync(0xFFFFFFFFu, r1 == r);
        unsigned b2 = __ballot_sync(0xFFFFFFFFu, r2 == r);
        unsigned b3 = __ballot_sync(0xFFFFFFFFu, r3 == r);
        if (hl == r) {
            int c = __popc(b0 & hm) + __popc(b1 & hm) + __popc(b2 & hm) + __popc(b3 & hm);
            myinv = 1.0f / (float)(c > 0 ? c : 1);
        }
    }
    // per-lane scales (convergent segment shuffles), zeroed/cleared for invalid slots
    float s0 = __shfl_sync(0xFFFFFFFFu, myinv, r0 & 7, 16); s0 = v0 ? s0 : 0.0f;
    float s1 = __shfl_sync(0xFFFFFFFFu, myinv, r1 & 7, 16); s1 = v1 ? s1 : 0.0f;
    float s2 = __shfl_sync(0xFFFFFFFFu, myinv, r2 & 7, 16); s2 = v2 ? s2 : 0.0f;
    float s3 = __shfl_sync(0xFFFFFFFFu, myinv, r3 & 7, 16); s3 = v3 ? s3 : 0.0f;
    int e0 = v0 ? e0r : 0, e1 = v1 ? e1r : 0, e2 = v2 ? e2r : 0, e3 = v3 ? e3r : 0;

    // two half2 slots per lane: 2hl, 2hl+1
    int sl0 = 2 * hl;
    int sl1 = sl0 + 1;
    int cl0 = ((sl0 & 7) << 3) + ((sl0 >> 3) << 1);
    int cl1 = ((sl1 & 7) << 3) + ((sl1 >> 3) << 1);
    float2 acc0 = *(const float2*)&out[(size_t)w * CC + cl0];
    float2 acc1 = *(const float2*)&out[(size_t)w * CC + cl1];
    const __half2* hv = (const __half2*)g_hall;

    // 8 batches of 8 edges: shuffles -> 8 independent loads -> accumulate (no guards)
#pragma unroll
    for (int batch = 0; batch < 8; batch++) {
        int base = batch * 8;
        if (base >= cnt) break;
        int ee = (batch < 2) ? e0 : (batch < 4) ? e1 : (batch < 6) ? e2 : e3;
        float ss = (batch < 2) ? s0 : (batch < 4) ? s1 : (batch < 6) ? s2 : s3;
        int off = (batch & 1) << 3;
        int eb[8]; float sb[8]; uint2 vb[8];
#pragma unroll
        for (int j = 0; j < 8; j++) {
            eb[j] = __shfl_sync(hm, ee, off + j, 16);
            sb[j] = __shfl_sync(hm, ss, off + j, 16);
        }
#pragma unroll
        for (int j = 0; j < 8; j++)
            vb[j] = *(const uint2*)(hv + (size_t)(eb[j] & IDXMASK) * 32 + sl0);
#pragma unroll
        for (int j = 0; j < 8; j++) {
            float2 f0 = __half22float2(*(__half2*)&vb[j].x);
            float2 f1 = __half22float2(*(__half2*)&vb[j].y);
            acc0.x += f0.x * sb[j]; acc0.y += f0.y * sb[j];
            acc1.x += f1.x * sb[j]; acc1.y += f1.y * sb[j];
        }
    }
    *(float2*)&out[(size_t)w * CC + cl0] = acc0;
    *(float2*)&out[(size_t)w * CC + cl1] = acc1;
}

// ---------------- launch ----------------
extern "C" void kernel_launch(void* const* d_in, const int* in_sizes, int n_in,
                              void* d_out, int out_size) {
    (void)in_sizes; (void)n_in; (void)out_size;
    const int*   ei    = (const int*)d_in[0];
    const int*   et    = (const int*)d_in[1];
    const float* W1    = (const float*)d_in[2];
    const float* root1 = (const float*)d_in[3];
    const float* b1    = (const float*)d_in[4];
    const float* W2    = (const float*)d_in[5];
    const float* root2 = (const float*)d_in[6];
    const float* b2    = (const float*)d_in[7];
    float* out = (float*)d_out;

    void* p_cursor = nullptr;
    cudaGetSymbolAddress(&p_cursor, g_cursor);
    cudaMemsetAsync(p_cursor, 0, NN * sizeof(int));

    k_perm<<<(EE + 255) / 256, 256>>>(ei, et, W2, root2);
    k_layer1<<<NN / 8, 256>>>(W1, root1, b1);
    cudaFuncSetAttribute(k_gemm, cudaFuncAttributeMaxDynamicSharedMemorySize, SM_TOTAL);
    k_gemm<<<dim3(NTILES, 3), 256, SM_TOTAL>>>(b2, out);
    k_layer2<<<2500, 256>>>(out);
}